// round 7
// baseline (speedup 1.0000x reference)
#include <cuda_runtime.h>
#include <stdint.h>
#include <math.h>

#define NB 2048
#define ND 256
#define NDT 768
#define HS 512
#define NBINW 1024               // u32 words per variable = 2048 u16 bins

// zero/static-initialized at module load; finish block resets them each run
__device__ double g_acc[8];      // [0]=mse sumsq, [1..7]=S1,S2,S3,S13,S23,S12,S123
__device__ double g_ck[14];      // ce,kl sums per 7 masks
__device__ unsigned int g_minbits[3] = {0xFFFFFFFFu, 0xFFFFFFFFu, 0xFFFFFFFFu};
__device__ unsigned int g_done;  // auto-wraps via atomicInc

__device__ __forceinline__ unsigned int fkey(float f) {
    unsigned int u = __float_as_uint(f);
    return (u & 0x80000000u) ? ~u : (u | 0x80000000u);
}
__device__ __forceinline__ float funkey(unsigned int u) {
    return __uint_as_float((u & 0x80000000u) ? (u & 0x7FFFFFFFu) : ~u);
}

// FMA-pipe exp (no MUFU)
__device__ __forceinline__ float fexp(float x) {
    float t = x * 1.44269504f;
    float fi = floorf(t);
    float f = t - fi;
    float p = 0.00134086f;
    p = fmaf(p, f, 0.00961812f);
    p = fmaf(p, f, 0.05550411f);
    p = fmaf(p, f, 0.24022651f);
    p = fmaf(p, f, 0.69314718f);
    p = fmaf(p, f, 1.0f);
    return __int_as_float(((int)fi + 127) << 23) * p;
}

// ---------------- kernel 1: global mins of d1/d2/d3 ----------------
__global__ void min_kernel(const float* __restrict__ d1, const float* __restrict__ d2,
                           const float* __restrict__ d3) {
    __shared__ float smn[3][8];
    int tid = blockIdx.x * blockDim.x + threadIdx.x;   // grid 512*256 = 131072
    int lane = threadIdx.x & 31, w = threadIdx.x >> 5;
    const float4* a1 = (const float4*)d1;
    const float4* a2 = (const float4*)d2;
    const float4* a3 = (const float4*)d3;
    float4 v1 = a1[tid], v2 = a2[tid], v3 = a3[tid];   // 131072 f4 exactly
    float mn[3];
    mn[0] = fminf(fminf(v1.x, v1.y), fminf(v1.z, v1.w));
    mn[1] = fminf(fminf(v2.x, v2.y), fminf(v2.z, v2.w));
    mn[2] = fminf(fminf(v3.x, v3.y), fminf(v3.z, v3.w));
    for (int o = 16; o; o >>= 1)
#pragma unroll
        for (int k = 0; k < 3; k++) mn[k] = fminf(mn[k], __shfl_xor_sync(0xffffffffu, mn[k], o));
    if (lane == 0) { smn[0][w] = mn[0]; smn[1][w] = mn[1]; smn[2][w] = mn[2]; }
    __syncthreads();
    if (threadIdx.x == 0) {
        float m0 = smn[0][0], m1 = smn[1][0], m2 = smn[2][0];
        for (int i = 1; i < 8; i++) {
            m0 = fminf(m0, smn[0][i]); m1 = fminf(m1, smn[1][i]); m2 = fminf(m2, smn[2][i]);
        }
        atomicMin(&g_minbits[0], fkey(m0));
        atomicMin(&g_minbits[1], fkey(m1));
        atomicMin(&g_minbits[2], fkey(m2));
    }
}

// packed-slot insert (u32): word = key<<9 | count, key <= 22 bits
__device__ __forceinline__ uint32_t hinsert(uint32_t* table, uint32_t key) {
    uint32_t h = (key * 2654435769u) >> 23;
    uint32_t packed = (key << 9) | 1u;
    for (;;) {
        uint32_t old = atomicCAS(&table[h], 0u, packed);
        if (old == 0u) return h;
        if ((old >> 9) == key) { atomicAdd(&table[h], 1u); return h; }
        h = (h + 1) & (HS - 1);
    }
}

// packed-slot insert (u64): word = key<<9 | count, key <= 33 bits
__device__ __forceinline__ uint32_t hinsert64(unsigned long long* table, unsigned long long key) {
    uint32_t h = (uint32_t)((key * 0x9E3779B97F4A7C15ull) >> 55);  // 9-bit hash
    unsigned long long packed = (key << 9) | 1ull;
    for (;;) {
        unsigned long long old = atomicCAS(&table[h], 0ull, packed);
        if (old == 0ull) return h;
        if ((old >> 9) == key) { atomicAdd(&table[h], 1ull); return h; }
        h = (h + 1) & (HS - 1);
    }
}

// ---------------- mega kernel: one block = one row (stats + entropy) + MSE slice ----------------
__global__ void __launch_bounds__(256) mega_kernel(
        const float* __restrict__ d1, const float* __restrict__ d2,
        const float* __restrict__ d3,
        const float* __restrict__ o1, const float* __restrict__ o2,
        const float* __restrict__ o3,
        const float* __restrict__ data, const float* __restrict__ outp,
        float* __restrict__ out) {
    __shared__ uint32_t cnt[3 * NBINW];        // 12 KB direct-mapped packed u16 single counts
    __shared__ uint32_t ptab[3 * HS];          // 6 KB pair tables
    __shared__ unsigned long long ttab[HS];    // 4 KB triple table (u64 packed)
    __shared__ float wred[6 * 8];              // warp maxes: mD1-3, mO1-3
    __shared__ float wsum[12 * 8];             // warp partial sums: (sD,tO,uD,sO) x 3
    __shared__ float stat18[18];
    __shared__ float ered[7 * 8];
    int bid = blockIdx.x, t = threadIdx.x;
    int lane = t & 31, w = t >> 5;
    int idx = bid * ND + t;

    // --- load row elements once (reused by stats AND labels) ---
    float e0 = d1[idx], e1 = d2[idx], e2 = d3[idx];
    float p0 = o1[idx], p1 = o2[idx], p2 = o3[idx];

    // --- MSE slice: 192 float4 per block ---
    {
        float s = 0.f;
        if (t < 192) {
            int i4 = bid * 192 + t;
            float4 x = ((const float4*)data)[i4];
            float4 y = ((const float4*)outp)[i4];
            float q0 = x.x - y.x, q1 = x.y - y.y, q2 = x.z - y.z, q3 = x.w - y.w;
            s = q0 * q0 + q1 * q1 + q2 * q2 + q3 * q3;
        }
        for (int o = 16; o; o >>= 1) s += __shfl_xor_sync(0xffffffffu, s, o);
        if (lane == 0 && w < 6) atomicAdd(&g_acc[0], (double)s);
    }

    // --- zero tables ---
    {
        uint4* cz = (uint4*)cnt;                     // 768 uint4
#pragma unroll
        for (int i = 0; i < 3; i++) cz[t + i * 256] = make_uint4(0, 0, 0, 0);
        uint4* pz = (uint4*)ptab;                    // 384 uint4
        pz[t & 255] = make_uint4(0, 0, 0, 0);        // redundant writes ok (t and t-256 same word? no)
        if (t < 128) pz[256 + t] = make_uint4(0, 0, 0, 0);
        uint4* tz = (uint4*)ttab;                    // 256 uint4
        if (t < 256) tz[t] = make_uint4(0, 0, 0, 0);
    }

    // --- labels from already-loaded elements ---
    float lo1 = floorf(funkey(g_minbits[0]));
    float lo2 = floorf(funkey(g_minbits[1]));
    float lo3 = floorf(funkey(g_minbits[2]));
    uint32_t l1 = (uint32_t)(int)floorf(__fdiv_rn(e0 - lo1, 0.01f));
    uint32_t l2 = (uint32_t)(int)floorf(__fdiv_rn(e1 - lo2, 0.01f));
    uint32_t l3 = (uint32_t)(int)floorf(__fdiv_rn(e2 - lo3, 0.01f));

    // --- stats: warp maxes (independent of tables) ---
    {
        float q[6] = {e0, e1, e2, p0, p1, p2};
#pragma unroll
        for (int k = 0; k < 6; k++) {
            float m = q[k];
            for (int o = 16; o; o >>= 1) m = fmaxf(m, __shfl_xor_sync(0xffffffffu, m, o));
            if (lane == 0) wred[k * 8 + w] = m;
        }
    }
    __syncthreads();   // barrier 1: tables zeroed + warp maxes visible

    // --- singles: one plain atomicAdd each ---
    atomicAdd(&cnt[0 * NBINW + (l1 >> 1)], (l1 & 1u) ? 0x10000u : 1u);
    atomicAdd(&cnt[1 * NBINW + (l2 >> 1)], (l2 & 1u) ? 0x10000u : 1u);
    atomicAdd(&cnt[2 * NBINW + (l3 >> 1)], (l3 & 1u) ? 0x10000u : 1u);

    // --- block maxes + exp partial sums ---
    float bm[6];
#pragma unroll
    for (int k = 0; k < 6; k++) {
        float m = wred[k * 8];
#pragma unroll
        for (int i = 1; i < 8; i++) m = fmaxf(m, wred[k * 8 + i]);
        bm[k] = m;
    }
    {
        float vals[12];
        float ex;
        ex = __expf(e0 - bm[0]); vals[0] = ex; vals[1] = ex * p0; vals[2]  = ex * e0; vals[3]  = fexp(p0 - bm[3]);
        ex = __expf(e1 - bm[1]); vals[4] = ex; vals[5] = ex * p1; vals[6]  = ex * e1; vals[7]  = fexp(p1 - bm[4]);
        ex = __expf(e2 - bm[2]); vals[8] = ex; vals[9] = ex * p2; vals[10] = ex * e2; vals[11] = fexp(p2 - bm[5]);
#pragma unroll
        for (int q = 0; q < 12; q++) {
            float s = vals[q];
            for (int o = 16; o; o >>= 1) s += __shfl_xor_sync(0xffffffffu, s, o);
            if (lane == 0) wsum[q * 8 + w] = s;
        }
    }
    __syncthreads();   // barrier 2: singles counted + warp sums visible

    // --- read single counts, candidate-pruned pair AND triple inserts (one round) ---
    uint32_t c1 = (cnt[0 * NBINW + (l1 >> 1)] >> ((l1 & 1u) * 16)) & 0xFFFFu;
    uint32_t c2 = (cnt[1 * NBINW + (l2 >> 1)] >> ((l2 & 1u) * 16)) & 0xFFFFu;
    uint32_t c3 = (cnt[2 * NBINW + (l3 >> 1)] >> ((l3 & 1u) * 16)) & 0xFFFFu;
    bool a13 = (c1 > 1u) & (c3 > 1u);
    bool a23 = (c2 > 1u) & (c3 > 1u);
    bool a12 = (c1 > 1u) & (c2 > 1u);
    bool a123 = a12 & (c3 > 1u);
    uint32_t h13 = 0, h23 = 0, h12 = 0, h123 = 0;
    if (a13) h13 = hinsert(ptab + 0 * HS, l1 | (l3 << 11));
    if (a23) h23 = hinsert(ptab + 1 * HS, l2 | (l3 << 11));
    if (a12) h12 = hinsert(ptab + 2 * HS, l1 | (l2 << 11));
    if (a123) h123 = hinsert64(ttab, (unsigned long long)l1 |
                                     ((unsigned long long)l2 << 11) |
                                     ((unsigned long long)l3 << 22));

    // --- meanwhile: combine warp sums/maxes into stat18 ---
    if (t < 12) {
        const int off[4] = {1, 2, 3, 5};   // sD, tO, uD, sO
        float s = 0.f;
#pragma unroll
        for (int i = 0; i < 8; i++) s += wsum[t * 8 + i];
        stat18[(t >> 2) * 6 + off[t & 3]] = s;
    } else if (t < 15) {
        stat18[(t - 12) * 6 + 0] = bm[t - 12];       // mD
    } else if (t < 18) {
        stat18[(t - 15) * 6 + 4] = bm[t - 15 + 3];   // mO
    }
    __syncthreads();   // barrier 3: pair/triple counts + stat18 ready

    // --- entropy per-element logs ---
    uint32_t c13 = a13 ? (ptab[0 * HS + h13] & 511u) : 1u;
    uint32_t c23 = a23 ? (ptab[1 * HS + h23] & 511u) : 1u;
    uint32_t c12 = a12 ? (ptab[2 * HS + h12] & 511u) : 1u;
    uint32_t c123 = a123 ? (uint32_t)(ttab[h123] & 511ull) : 1u;
    float A[7];
    A[0] = (c1 > 1u) ? logf((float)c1) : 0.f;
    A[1] = (c2 > 1u) ? logf((float)c2) : 0.f;
    A[2] = (c3 > 1u) ? logf((float)c3) : 0.f;
    A[3] = (c13 > 1u) ? logf((float)c13) : 0.f;
    A[4] = (c23 > 1u) ? logf((float)c23) : 0.f;
    A[5] = (c12 > 1u) ? logf((float)c12) : 0.f;
    A[6] = (c123 > 1u) ? logf((float)c123) : 0.f;
#pragma unroll
    for (int k = 0; k < 7; k++) {
        float x = A[k];
        for (int o = 16; o; o >>= 1) x += __shfl_xor_sync(0xffffffffu, x, o);
        if (lane == 0) ered[k * 8 + w] = x;
    }

    // --- hsoft for this row: threads 32..38 (warp 1), uses stat18 ---
    if (t >= 32 && t < 39) {
        const int masks[7] = {1, 2, 4, 5, 6, 3, 7};
        int m = masks[t - 32];
        float M = -INFINITY, MO = -INFINITY;
#pragma unroll
        for (int k = 0; k < 3; k++)
            if (m & (1 << k)) { M = fmaxf(M, stat18[k * 6 + 0]); MO = fmaxf(MO, stat18[k * 6 + 4]); }
        float S = 0.f, T = 0.f, U = 0.f, SO = 0.f;
#pragma unroll
        for (int k = 0; k < 3; k++)
            if (m & (1 << k)) {
                float wt = __expf(stat18[k * 6 + 0] - M);
                S += stat18[k * 6 + 1] * wt;
                T += stat18[k * 6 + 2] * wt;
                U += stat18[k * 6 + 3] * wt;
                SO += stat18[k * 6 + 5] * __expf(stat18[k * 6 + 4] - MO);
            }
        float lseD = M + logf(S);
        float lseO = MO + logf(SO);
        float Spo = T / S, Spd = U / S;
        atomicAdd(&g_ck[t - 32], (double)(lseO - Spo));                        // ce
        atomicAdd(&g_ck[7 + t - 32], (double)((Spd - lseD) - (Spo - lseO)));   // kl
    }
    __syncthreads();   // barrier 4: ered ready

    if (t < 7) {
        double a = 0.0;
#pragma unroll
        for (int i = 0; i < 8; i++) a += (double)ered[t * 8 + i];
        // row entropy H = log(256) - A/256
        atomicAdd(&g_acc[1 + t], 5.545177444479562 - a * (1.0 / 256.0));
    }

    // ======== last block: assemble scalar + reset state for next replay ========
    __syncthreads();
    if (t == 0) {
        __threadfence();
        unsigned int old = atomicInc(&g_done, NB - 1);   // wraps to 0 on last
        if (old == NB - 1) {
            const int masks[7] = {1, 2, 4, 5, 6, 3, 7};
            double Hout[7];
            for (int s = 0; s < 7; s++) {
                int C = ND * __popc(masks[s]);
                Hout[s] = g_ck[s] / (double)NB - g_ck[7 + s] / ((double)NB * (double)C);
            }
            double Hd1 = g_acc[1] / NB, Hd2 = g_acc[2] / NB, Hd3 = g_acc[3] / NB;
            double Hin13 = g_acc[4] / NB, Hin23 = g_acc[5] / NB, Hin12 = g_acc[6] / NB;
            double H1 = Hd1 - Hout[0];
            double H2 = Hd2 - Hout[1];
            double H3 = Hd3 - Hout[2];
            double data13 = Hd1 + Hd3 - Hin13;
            double data23 = Hd2 + Hd3 - Hin23;
            double data12 = Hd1 + Hd2 - Hin12;
            double lab13 = Hout[0] + Hout[2] - Hout[3];
            double lab23 = Hout[1] + Hout[2] - Hout[4];
            double lab12 = Hout[0] + Hout[1] - Hout[5];
            double MI13 = lab13 - data13, MI23 = lab23 - data23, MI12 = lab12 - data12;
            double aveDataCMI = g_acc[4] + g_acc[5] - g_acc[3] - g_acc[7];
            double aveLabCMI = Hout[4] - Hout[2] + Hout[3] - Hout[6];
            double CMI = aveLabCMI - aveDataCMI;
            double mse = 0.5 * (g_acc[0] / ((double)NB * (double)NDT));
            double loss = 0.5 * mse
                        + 0.25 * (H1 * H1 + H2 * H2 + H3 * H3)
                        + 0.25 * (MI13 * MI13 + MI23 * MI23 + MI12 * MI12 + CMI * CMI);
            out[0] = (float)loss;
            // reset for next graph replay
            for (int i = 0; i < 8; i++) g_acc[i] = 0.0;
            for (int i = 0; i < 14; i++) g_ck[i] = 0.0;
            g_minbits[0] = 0xFFFFFFFFu; g_minbits[1] = 0xFFFFFFFFu; g_minbits[2] = 0xFFFFFFFFu;
        }
    }
}

extern "C" void kernel_launch(void* const* d_in, const int* in_sizes, int n_in,
                              void* d_out, int out_size) {
    (void)in_sizes; (void)n_in; (void)out_size;
    const float* data  = (const float*)d_in[0];
    const float* data1 = (const float*)d_in[1];
    const float* data2 = (const float*)d_in[2];
    const float* data3 = (const float*)d_in[3];
    const float* out1  = (const float*)d_in[4];
    const float* out2  = (const float*)d_in[5];
    const float* out3  = (const float*)d_in[6];
    const float* outp  = (const float*)d_in[7];

    min_kernel<<<512, 256>>>(data1, data2, data3);
    mega_kernel<<<NB, 256>>>(data1, data2, data3, out1, out2, out3, data, outp, (float*)d_out);
}

// round 8
// speedup vs baseline: 1.4753x; 1.4753x over previous
#include <cuda_runtime.h>
#include <stdint.h>
#include <math.h>

#define NB 2048
#define ND 256
#define NDT 768
#define HSP 256                  // pair/triple hash slots
#define SBLK 256                 // stats blocks (8 rows each)
#define TOTBLK (NB + SBLK)

// zero/static-initialized at module load; finish block resets them each run
__device__ double g_acc[8];      // [0]=mse sumsq, [1..7]=S1,S2,S3,S13,S23,S12,S123
__device__ double g_ck[14];      // ce,kl sums per 7 masks
__device__ unsigned int g_minbits[3] = {0xFFFFFFFFu, 0xFFFFFFFFu, 0xFFFFFFFFu};
__device__ unsigned int g_done;  // auto-wraps via atomicInc

__device__ __forceinline__ unsigned int fkey(float f) {
    unsigned int u = __float_as_uint(f);
    return (u & 0x80000000u) ? ~u : (u | 0x80000000u);
}
__device__ __forceinline__ float funkey(unsigned int u) {
    return __uint_as_float((u & 0x80000000u) ? (u & 0x7FFFFFFFu) : ~u);
}

// FMA-pipe exp (no MUFU)
__device__ __forceinline__ float fexp(float x) {
    float t = x * 1.44269504f;
    float fi = floorf(t);
    float f = t - fi;
    float p = 0.00134086f;
    p = fmaf(p, f, 0.00961812f);
    p = fmaf(p, f, 0.05550411f);
    p = fmaf(p, f, 0.24022651f);
    p = fmaf(p, f, 0.69314718f);
    p = fmaf(p, f, 1.0f);
    return __int_as_float(((int)fi + 127) << 23) * p;
}

// ---------------- kernel 1: global mins of d1/d2/d3 ----------------
__global__ void min_kernel(const float* __restrict__ d1, const float* __restrict__ d2,
                           const float* __restrict__ d3) {
    __shared__ float smn[3][8];
    int tid = blockIdx.x * blockDim.x + threadIdx.x;   // grid 512*256 = 131072
    int lane = threadIdx.x & 31, w = threadIdx.x >> 5;
    const float4* a1 = (const float4*)d1;
    const float4* a2 = (const float4*)d2;
    const float4* a3 = (const float4*)d3;
    float4 v1 = a1[tid], v2 = a2[tid], v3 = a3[tid];   // 131072 f4 exactly
    float mn[3];
    mn[0] = fminf(fminf(v1.x, v1.y), fminf(v1.z, v1.w));
    mn[1] = fminf(fminf(v2.x, v2.y), fminf(v2.z, v2.w));
    mn[2] = fminf(fminf(v3.x, v3.y), fminf(v3.z, v3.w));
    for (int o = 16; o; o >>= 1)
#pragma unroll
        for (int k = 0; k < 3; k++) mn[k] = fminf(mn[k], __shfl_xor_sync(0xffffffffu, mn[k], o));
    if (lane == 0) { smn[0][w] = mn[0]; smn[1][w] = mn[1]; smn[2][w] = mn[2]; }
    __syncthreads();
    if (threadIdx.x == 0) {
        float m0 = smn[0][0], m1 = smn[1][0], m2 = smn[2][0];
        for (int i = 1; i < 8; i++) {
            m0 = fminf(m0, smn[0][i]); m1 = fminf(m1, smn[1][i]); m2 = fminf(m2, smn[2][i]);
        }
        atomicMin(&g_minbits[0], fkey(m0));
        atomicMin(&g_minbits[1], fkey(m1));
        atomicMin(&g_minbits[2], fkey(m2));
    }
}

// packed-slot insert (u32, 256 slots): word = key<<9 | count, key <= 22 bits
__device__ __forceinline__ uint32_t hinsert8(uint32_t* table, uint32_t key) {
    uint32_t h = (key * 2654435769u) >> 24;
    uint32_t packed = (key << 9) | 1u;
    for (;;) {
        uint32_t old = atomicCAS(&table[h], 0u, packed);
        if (old == 0u) return h;
        if ((old >> 9) == key) { atomicAdd(&table[h], 1u); return h; }
        h = (h + 1) & (HSP - 1);
    }
}

// packed-slot insert (u64, 256 slots): word = key<<9 | count, key <= 33 bits
__device__ __forceinline__ uint32_t hinsert64(unsigned long long* table, unsigned long long key) {
    uint32_t h = (uint32_t)((key * 0x9E3779B97F4A7C15ull) >> 56);
    unsigned long long packed = (key << 9) | 1ull;
    for (;;) {
        unsigned long long old = atomicCAS(&table[h], 0ull, packed);
        if (old == 0ull) return h;
        if ((old >> 9) == key) { atomicAdd(&table[h], 1ull); return h; }
        h = (h + 1) & (HSP - 1);
    }
}

// ---------------- mega kernel: stats blocks (0..255) + entropy blocks (256..2303) ----------------
// pool layout (u32 words): [0,1536) u8-packed single counts (3 vars x 512 words x 4 bins)
//                          [1536,2304) pair tables (3 x 256)
//                          [2304,2816) triple table (256 x u64)
__global__ void __launch_bounds__(256, 8) mega_kernel(
        const float* __restrict__ d1, const float* __restrict__ d2,
        const float* __restrict__ d3,
        const float* __restrict__ o1, const float* __restrict__ o2,
        const float* __restrict__ o3,
        const float* __restrict__ data, const float* __restrict__ outp,
        float* __restrict__ out) {
    __shared__ __align__(16) uint32_t pool[2816];   // 11 KB
    __shared__ float ered[7 * 8];
    __shared__ float sstat[8][18];
    __shared__ double sacc[14];
    int bid = blockIdx.x, t = threadIdx.x;
    int lane = t & 31, w = t >> 5;

    if (bid < SBLK) {
        // ======== stats path: fused MSE slice + 8 rows (one warp per row) ========
        if (t < 14) sacc[t] = 0.0;
        {
            const float4* da = (const float4*)data;
            const float4* db = (const float4*)outp;
            float s = 0.f;
#pragma unroll
            for (int i = 0; i < 6; i++) {
                int idx = bid * 256 + t + i * 65536;
                float4 x = da[idx], y = db[idx];
                float q0 = x.x - y.x, q1 = x.y - y.y, q2 = x.z - y.z, q3 = x.w - y.w;
                s += q0 * q0 + q1 * q1 + q2 * q2 + q3 * q3;
            }
            for (int o = 16; o; o >>= 1) s += __shfl_xor_sync(0xffffffffu, s, o);
            if (lane == 0) atomicAdd(&g_acc[0], (double)s);
        }
        int gw = bid * 8 + w;
        const float* ds[3] = {d1, d2, d3};
        const float* os[3] = {o1, o2, o3};
#pragma unroll
        for (int k = 0; k < 3; k++) {
            const float* dp = ds[k] + gw * ND;
            const float* op = os[k] + gw * ND;
            // pass 1: maxes
            float mD = -INFINITY, mO = -INFINITY;
#pragma unroll
            for (int i = 0; i < 8; i++) {
                mD = fmaxf(mD, dp[lane + 32 * i]);
                mO = fmaxf(mO, op[lane + 32 * i]);
            }
            for (int o = 16; o; o >>= 1) {
                mD = fmaxf(mD, __shfl_xor_sync(0xffffffffu, mD, o));
                mO = fmaxf(mO, __shfl_xor_sync(0xffffffffu, mO, o));
            }
            // pass 2: exp sums (reload, L1-hot)
            float sD = 0.f, tO = 0.f, uD = 0.f, sO = 0.f;
#pragma unroll
            for (int i = 0; i < 8; i++) {
                float a = dp[lane + 32 * i], b = op[lane + 32 * i];
                float e = __expf(a - mD);       // MUFU
                sD += e; tO += e * b; uD += e * a;
                sO += fexp(b - mO);             // FMA
            }
            for (int o = 16; o; o >>= 1) {
                sD += __shfl_xor_sync(0xffffffffu, sD, o);
                tO += __shfl_xor_sync(0xffffffffu, tO, o);
                uD += __shfl_xor_sync(0xffffffffu, uD, o);
                sO += __shfl_xor_sync(0xffffffffu, sO, o);
            }
            if (lane == 0) {
                sstat[w][k * 6 + 0] = mD; sstat[w][k * 6 + 1] = sD;
                sstat[w][k * 6 + 2] = tO; sstat[w][k * 6 + 3] = uD;
                sstat[w][k * 6 + 4] = mO; sstat[w][k * 6 + 5] = sO;
            }
        }
        __syncthreads();
        // hsoft: 8 rows x 7 masks = 56 threads
        if (t < 56) {
            const int masks[7] = {1, 2, 4, 5, 6, 3, 7};
            int r = t / 7, j = t - r * 7;
            int m = masks[j];
            const float* st = sstat[r];
            float M = -INFINITY, MO = -INFINITY;
#pragma unroll
            for (int k = 0; k < 3; k++)
                if (m & (1 << k)) { M = fmaxf(M, st[k * 6 + 0]); MO = fmaxf(MO, st[k * 6 + 4]); }
            float S = 0.f, T = 0.f, U = 0.f, SO = 0.f;
#pragma unroll
            for (int k = 0; k < 3; k++)
                if (m & (1 << k)) {
                    float wt = __expf(st[k * 6 + 0] - M);
                    S += st[k * 6 + 1] * wt;
                    T += st[k * 6 + 2] * wt;
                    U += st[k * 6 + 3] * wt;
                    SO += st[k * 6 + 5] * __expf(st[k * 6 + 4] - MO);
                }
            float lseD = M + logf(S);
            float lseO = MO + logf(SO);
            float Spo = T / S, Spd = U / S;
            atomicAdd(&sacc[j], (double)(lseO - Spo));                      // ce
            atomicAdd(&sacc[7 + j], (double)((Spd - lseD) - (Spo - lseO))); // kl
        }
        __syncthreads();
        if (t < 14) atomicAdd(&g_ck[t], sacc[t]);
    } else {
        // ======== entropy path: one row ========
        int row = bid - SBLK;
        int idx = row * ND + t;
        float lo1 = floorf(funkey(g_minbits[0]));
        float lo2 = floorf(funkey(g_minbits[1]));
        float lo3 = floorf(funkey(g_minbits[2]));
        uint32_t l1 = (uint32_t)(int)floorf(__fdiv_rn(d1[idx] - lo1, 0.01f));
        uint32_t l2 = (uint32_t)(int)floorf(__fdiv_rn(d2[idx] - lo2, 0.01f));
        uint32_t l3 = (uint32_t)(int)floorf(__fdiv_rn(d3[idx] - lo3, 0.01f));

        // zero pool: 704 uint4
        {
            uint4* pz = (uint4*)pool;
            pz[t] = make_uint4(0, 0, 0, 0);
            pz[t + 256] = make_uint4(0, 0, 0, 0);
            if (t < 192) pz[t + 512] = make_uint4(0, 0, 0, 0);
        }
        __syncthreads();

        // singles: one plain atomicAdd each into u8-packed bins
        atomicAdd(&pool[0 * 512 + (l1 >> 2)], 1u << (8u * (l1 & 3u)));
        atomicAdd(&pool[1 * 512 + (l2 >> 2)], 1u << (8u * (l2 & 3u)));
        atomicAdd(&pool[2 * 512 + (l3 >> 2)], 1u << (8u * (l3 & 3u)));
        __syncthreads();

        uint32_t c1 = (pool[0 * 512 + (l1 >> 2)] >> (8u * (l1 & 3u))) & 255u;
        uint32_t c2 = (pool[1 * 512 + (l2 >> 2)] >> (8u * (l2 & 3u))) & 255u;
        uint32_t c3 = (pool[2 * 512 + (l3 >> 2)] >> (8u * (l3 & 3u))) & 255u;

        // pairs + triple in ONE round (singles-only pruning)
        uint32_t* ptab = pool + 1536;
        unsigned long long* ttab = (unsigned long long*)(pool + 2304);
        bool a13 = (c1 > 1u) & (c3 > 1u);
        bool a23 = (c2 > 1u) & (c3 > 1u);
        bool a12 = (c1 > 1u) & (c2 > 1u);
        bool a123 = a12 & (c3 > 1u);
        uint32_t h13 = 0, h23 = 0, h12 = 0, h123 = 0;
        if (a13) h13 = hinsert8(ptab + 0 * HSP, l1 | (l3 << 11));
        if (a23) h23 = hinsert8(ptab + 1 * HSP, l2 | (l3 << 11));
        if (a12) h12 = hinsert8(ptab + 2 * HSP, l1 | (l2 << 11));
        if (a123) h123 = hinsert64(ttab, (unsigned long long)l1 |
                                         ((unsigned long long)l2 << 11) |
                                         ((unsigned long long)l3 << 22));
        __syncthreads();

        uint32_t c13 = a13 ? (ptab[0 * HSP + h13] & 511u) : 1u;
        uint32_t c23 = a23 ? (ptab[1 * HSP + h23] & 511u) : 1u;
        uint32_t c12 = a12 ? (ptab[2 * HSP + h12] & 511u) : 1u;
        uint32_t c123 = a123 ? (uint32_t)(ttab[h123] & 511ull) : 1u;

        float A[7];
        A[0] = (c1 > 1u) ? logf((float)c1) : 0.f;
        A[1] = (c2 > 1u) ? logf((float)c2) : 0.f;
        A[2] = (c3 > 1u) ? logf((float)c3) : 0.f;
        A[3] = (c13 > 1u) ? logf((float)c13) : 0.f;
        A[4] = (c23 > 1u) ? logf((float)c23) : 0.f;
        A[5] = (c12 > 1u) ? logf((float)c12) : 0.f;
        A[6] = (c123 > 1u) ? logf((float)c123) : 0.f;
#pragma unroll
        for (int k = 0; k < 7; k++) {
            float x = A[k];
            for (int o = 16; o; o >>= 1) x += __shfl_xor_sync(0xffffffffu, x, o);
            if (lane == 0) ered[k * 8 + w] = x;
        }
        __syncthreads();
        if (t < 7) {
            double a = 0.0;
#pragma unroll
            for (int i = 0; i < 8; i++) a += (double)ered[t * 8 + i];
            // row entropy H = log(256) - A/256
            atomicAdd(&g_acc[1 + t], 5.545177444479562 - a * (1.0 / 256.0));
        }
    }

    // ======== last block: assemble scalar + reset state for next replay ========
    __syncthreads();
    if (t == 0) {
        __threadfence();
        unsigned int old = atomicInc(&g_done, TOTBLK - 1);   // wraps to 0 on last
        if (old == TOTBLK - 1) {
            const int masks[7] = {1, 2, 4, 5, 6, 3, 7};
            double Hout[7];
            for (int s = 0; s < 7; s++) {
                int C = ND * __popc(masks[s]);
                Hout[s] = g_ck[s] / (double)NB - g_ck[7 + s] / ((double)NB * (double)C);
            }
            double Hd1 = g_acc[1] / NB, Hd2 = g_acc[2] / NB, Hd3 = g_acc[3] / NB;
            double Hin13 = g_acc[4] / NB, Hin23 = g_acc[5] / NB, Hin12 = g_acc[6] / NB;
            double H1 = Hd1 - Hout[0];
            double H2 = Hd2 - Hout[1];
            double H3 = Hd3 - Hout[2];
            double data13 = Hd1 + Hd3 - Hin13;
            double data23 = Hd2 + Hd3 - Hin23;
            double data12 = Hd1 + Hd2 - Hin12;
            double lab13 = Hout[0] + Hout[2] - Hout[3];
            double lab23 = Hout[1] + Hout[2] - Hout[4];
            double lab12 = Hout[0] + Hout[1] - Hout[5];
            double MI13 = lab13 - data13, MI23 = lab23 - data23, MI12 = lab12 - data12;
            double aveDataCMI = g_acc[4] + g_acc[5] - g_acc[3] - g_acc[7];
            double aveLabCMI = Hout[4] - Hout[2] + Hout[3] - Hout[6];
            double CMI = aveLabCMI - aveDataCMI;
            double mse = 0.5 * (g_acc[0] / ((double)NB * (double)NDT));
            double loss = 0.5 * mse
                        + 0.25 * (H1 * H1 + H2 * H2 + H3 * H3)
                        + 0.25 * (MI13 * MI13 + MI23 * MI23 + MI12 * MI12 + CMI * CMI);
            out[0] = (float)loss;
            // reset for next graph replay
            for (int i = 0; i < 8; i++) g_acc[i] = 0.0;
            for (int i = 0; i < 14; i++) g_ck[i] = 0.0;
            g_minbits[0] = 0xFFFFFFFFu; g_minbits[1] = 0xFFFFFFFFu; g_minbits[2] = 0xFFFFFFFFu;
        }
    }
}

extern "C" void kernel_launch(void* const* d_in, const int* in_sizes, int n_in,
                              void* d_out, int out_size) {
    (void)in_sizes; (void)n_in; (void)out_size;
    const float* data  = (const float*)d_in[0];
    const float* data1 = (const float*)d_in[1];
    const float* data2 = (const float*)d_in[2];
    const float* data3 = (const float*)d_in[3];
    const float* out1  = (const float*)d_in[4];
    const float* out2  = (const float*)d_in[5];
    const float* out3  = (const float*)d_in[6];
    const float* outp  = (const float*)d_in[7];

    min_kernel<<<512, 256>>>(data1, data2, data3);
    mega_kernel<<<TOTBLK, 256>>>(data1, data2, data3, out1, out2, out3, data, outp, (float*)d_out);
}